// round 12
// baseline (speedup 1.0000x reference)
#include <cuda_runtime.h>
#include <cstdint>

// FHE BSGS rotate/mul/accumulate. Fixed shapes: x[64,65536] f32, diag[16,65536] f32,
// stride=1, reps=1 -> out[b,s] = sum_t x[b,(s2+2^t)&65535] * diag[t,s2], s2 = s^32768.
// R11 skeleton (tap-outer / batch-inner, one-shot smem stage) + software pipelining
// of dv and far-tap loads so no load latency sits on the critical path.
#define SLOTS 65536
#define SQ    (SLOTS / 4)     // 16384 quads per row
#define QM    (SQ - 1)
#define BATCH 64
#define BPC   4               // batches per CTA (all staged at once)
#define TPB   256             // 1 output quad per thread -> 256-quad tile
#define NEARQ 768             // near union: 256 tile + 512 reach (shifts <= 2048 slots)

typedef unsigned long long u64;

__device__ __forceinline__ void cpasync16(uint32_t saddr, const float4* g) {
    asm volatile("cp.async.cg.shared.global [%0], [%1], 16;\n" :: "r"(saddr), "l"(g));
}
__device__ __forceinline__ void cp_commit() { asm volatile("cp.async.commit_group;\n"); }
__device__ __forceinline__ void cp_wait0()  { asm volatile("cp.async.wait_group 0;\n"); }

__device__ __forceinline__ u64 fma2(u64 x, u64 d, u64 a) {
    u64 r; asm("fma.rn.f32x2 %0, %1, %2, %3;" : "=l"(r) : "l"(x), "l"(d), "l"(a)); return r;
}
__device__ __forceinline__ u64 pack2(float lo, float hi) {
    u64 r; asm("mov.b64 %0, {%1, %2};" : "=l"(r) : "f"(lo), "f"(hi)); return r;
}

__global__ __launch_bounds__(TPB, 3)
void fhe_bsgs_tb2(const float* __restrict__ x,
                  const float* __restrict__ diag,
                  float* __restrict__ out)
{
    __shared__ float4 sx[BPC][NEARQ];   // 49152 B

    const int tid = threadIdx.x;
    const int Sq  = blockIdx.x * TPB + tid;     // output quad
    const int Tq  = (blockIdx.x * TPB) ^ 8192;  // tile base in s2 space (256-aligned)
    const int q2  = Tq + tid;                   // rolled quad for this thread
    const int b0  = blockIdx.y * BPC;

    const float4*     x4 = reinterpret_cast<const float4*>(x);
    const ulonglong2* x8 = reinterpret_cast<const ulonglong2*>(x);
    const float4*     d4 = reinterpret_cast<const float4*>(diag);
    const ulonglong2* d8 = reinterpret_cast<const ulonglong2*>(diag);

    // One-shot stage: near unions for all BPC batches (12 cp.asyncs/thread).
    #pragma unroll
    for (int b = 0; b < BPC; b++) {
        const float4* __restrict__ xb = x4 + (size_t)(b0 + b) * SQ;
        const uint32_t sb = (uint32_t)__cvta_generic_to_shared(&sx[b][0]);
        #pragma unroll
        for (int r = 0; r < 3; r++) {
            const int k = tid + 256 * r;
            cpasync16(sb + k * 16, xb + ((Tq + k) & QM));
        }
    }
    cp_commit();

    // ---- Independent loads issued UNDER the staging wait ----
    const float4 dvs0 = d4[0 * SQ + q2];
    const float4 dvs1 = d4[1 * SQ + q2];
    const float4 dvs2 = d4[2 * SQ + q2];
    ulonglong2 dv_next = d8[3 * SQ + q2];       // dv for t=3

    // Far tap 12 prefetch (dv + 4 batch X), consumed after the near loop.
    ulonglong2 dvF = d8[12 * SQ + q2];
    const unsigned qf12 = (unsigned)(q2 + (1 << 10)) & QM;
    ulonglong2 XF[BPC];
    #pragma unroll
    for (int b = 0; b < BPC; b++)
        XF[b] = x8[(size_t)(b0 + b) * SQ + qf12];

    cp_wait0();
    __syncthreads();     // the only barrier in the kernel

    u64 accLo[BPC], accHi[BPC];

    // ---- t=0..2 (misaligned windows) from smem ----
    #pragma unroll
    for (int b = 0; b < BPC; b++) {
        const float4 A  = sx[b][tid];
        const float4 Bv = sx[b][tid + 1];
        float s0, s1, s2, s3;
        s0 = A.y  * dvs0.x;               // t=0: (A.y,A.z,A.w,B.x)
        s1 = A.z  * dvs0.y;
        s2 = A.w  * dvs0.z;
        s3 = Bv.x * dvs0.w;
        s0 = fmaf(A.z,  dvs1.x, s0);      // t=1: (A.z,A.w,B.x,B.y)
        s1 = fmaf(A.w,  dvs1.y, s1);
        s2 = fmaf(Bv.x, dvs1.z, s2);
        s3 = fmaf(Bv.y, dvs1.w, s3);
        s0 = fmaf(Bv.x, dvs2.x, s0);      // t=2: B
        s1 = fmaf(Bv.y, dvs2.y, s1);
        s2 = fmaf(Bv.z, dvs2.z, s2);
        s3 = fmaf(Bv.w, dvs2.w, s3);
        accLo[b] = pack2(s0, s1);
        accHi[b] = pack2(s2, s3);
    }

    // ---- t=3..11 (offsets 2..512 quads) from smem; dv pipelined one tap ahead ----
    #pragma unroll
    for (int t = 3; t <= 11; t++) {
        const ulonglong2 dv = dv_next;
        if (t < 11)
            dv_next = d8[(t + 1) * SQ + q2];     // prefetch next tap's dv
        const int off = tid + (1 << (t - 2));
        #pragma unroll
        for (int b = 0; b < BPC; b++) {
            const ulonglong2 X = *reinterpret_cast<const ulonglong2*>(&sx[b][off]);
            accLo[b] = fma2(X.x, dv.x, accLo[b]);
            accHi[b] = fma2(X.y, dv.y, accHi[b]);
        }
    }

    // ---- t=12..15 (offsets 1024..8192 quads): direct LDG, one-tap-ahead rotation ----
    #pragma unroll
    for (int t = 12; t <= 15; t++) {
        const ulonglong2 dv = dvF;
        ulonglong2 Xc[BPC];
        #pragma unroll
        for (int b = 0; b < BPC; b++) Xc[b] = XF[b];

        if (t < 15) {                            // prefetch tap t+1 under tap t's FMAs
            dvF = d8[(t + 1) * SQ + q2];
            const unsigned qf = (unsigned)(q2 + (1 << (t - 1))) & QM;
            #pragma unroll
            for (int b = 0; b < BPC; b++)
                XF[b] = x8[(size_t)(b0 + b) * SQ + qf];
        }

        #pragma unroll
        for (int b = 0; b < BPC; b++) {
            accLo[b] = fma2(Xc[b].x, dv.x, accLo[b]);
            accHi[b] = fma2(Xc[b].y, dv.y, accHi[b]);
        }
    }

    #pragma unroll
    for (int b = 0; b < BPC; b++)
        reinterpret_cast<ulonglong2*>(out)[(size_t)(b0 + b) * SQ + Sq] =
            make_ulonglong2(accLo[b], accHi[b]);
}

extern "C" void kernel_launch(void* const* d_in, const int* in_sizes, int n_in,
                              void* d_out, int out_size)
{
    const float* x    = (const float*)d_in[0];
    const float* diag = (const float*)d_in[1];
    float* out = (float*)d_out;

    dim3 grid(SQ / TPB, BATCH / BPC);   // (64 tiles, 16 batch-groups) = 1024 CTAs
    fhe_bsgs_tb2<<<grid, TPB>>>(x, diag, out);
}